// round 1
// baseline (speedup 1.0000x reference)
#include <cuda_runtime.h>
#include <cuda_bf16.h>

#define D_MODEL 1024
#define HEADS   16
#define DK      64
#define D_FF    4096
#define BB      2
#define SS      2048
#define NTOK    (BB * SS)        // 4096
#define LN_EPS  1e-6f
#define NEGV    (-1e9f)

// ---------------- scratch (device globals; no runtime allocation) -----------
__device__ float g_Q  [NTOK * D_MODEL];
__device__ float g_Kb [NTOK * D_MODEL];
__device__ float g_V  [NTOK * D_MODEL];
__device__ float g_sc [134217728];          // B*H*S*S = 2*16*2048*2048 (512 MB)
__device__ float g_ctx[NTOK * D_MODEL];
__device__ float g_t1 [NTOK * D_MODEL];
__device__ float g_x1 [NTOK * D_MODEL];
__device__ float g_h  [NTOK * D_FF];
__device__ float g_t2 [NTOK * D_MODEL];

// ---------------- generic batched SGEMM -------------------------------------
// C[m,n] = scale * sum_k A[m,k] * B(k,n)   (B row-major K x N, or N x K if TRANSB)
// EPI bits: 1 = +bias[n], 2 = relu, 4 = +resid[m*ldc+n]
#define EPI_BIAS  1
#define EPI_RELU  2
#define EPI_RESID 4

template<int TRANSB, int EPI>
__global__ void __launch_bounds__(256)
sgemm_k(const float* __restrict__ A, const float* __restrict__ B,
        float* __restrict__ C, int M, int N, int K,
        int lda, int ldb, int ldc,
        long long offAh, long long offAb,
        long long offBh, long long offBb,
        long long offCh, long long offCb, int batchH,
        float scale, const float* __restrict__ bias,
        const float* __restrict__ resid)
{
    const int z  = blockIdx.z;
    const int bb = z / batchH, hh = z % batchH;
    A += bb * offAb + hh * offAh;
    B += bb * offBb + hh * offBh;
    C += bb * offCb + hh * offCh;

    __shared__ float As[8][128];
    __shared__ float Bs[8][128];

    const int tid  = threadIdx.x;
    const int row0 = blockIdx.y * 128;
    const int col0 = blockIdx.x * 128;
    const int ty   = tid >> 4;     // 0..15
    const int tx   = tid & 15;     // 0..15

    float acc[8][8];
#pragma unroll
    for (int i = 0; i < 8; i++)
#pragma unroll
        for (int j = 0; j < 8; j++) acc[i][j] = 0.f;

    for (int k0 = 0; k0 < K; k0 += 8) {
        // A tile: 128 rows x 8 k
#pragma unroll
        for (int i = 0; i < 4; i++) {
            int idx = tid + i * 256;
            int m = idx >> 3, kk = idx & 7;
            int gm = row0 + m, gk = k0 + kk;
            As[kk][m] = (gm < M && gk < K) ? A[(long long)gm * lda + gk] : 0.f;
        }
        // B tile: 8 k x 128 n
#pragma unroll
        for (int i = 0; i < 4; i++) {
            int idx = tid + i * 256;
            if (TRANSB) {
                int n = idx >> 3, kk = idx & 7;
                int gn = col0 + n, gk = k0 + kk;
                Bs[kk][n] = (gn < N && gk < K) ? B[(long long)gn * ldb + gk] : 0.f;
            } else {
                int kk = idx >> 7, n = idx & 127;
                int gn = col0 + n, gk = k0 + kk;
                Bs[kk][n] = (gn < N && gk < K) ? B[(long long)gk * ldb + gn] : 0.f;
            }
        }
        __syncthreads();

#pragma unroll
        for (int kk = 0; kk < 8; kk++) {
            float a[8], b[8];
            float4 a0 = *(const float4*)&As[kk][ty * 8];
            float4 a1 = *(const float4*)&As[kk][ty * 8 + 4];
            float4 b0 = *(const float4*)&Bs[kk][tx * 8];
            float4 b1 = *(const float4*)&Bs[kk][tx * 8 + 4];
            a[0]=a0.x; a[1]=a0.y; a[2]=a0.z; a[3]=a0.w;
            a[4]=a1.x; a[5]=a1.y; a[6]=a1.z; a[7]=a1.w;
            b[0]=b0.x; b[1]=b0.y; b[2]=b0.z; b[3]=b0.w;
            b[4]=b1.x; b[5]=b1.y; b[6]=b1.z; b[7]=b1.w;
#pragma unroll
            for (int i = 0; i < 8; i++)
#pragma unroll
                for (int j = 0; j < 8; j++)
                    acc[i][j] = fmaf(a[i], b[j], acc[i][j]);
        }
        __syncthreads();
    }

#pragma unroll
    for (int i = 0; i < 8; i++) {
        int gm = row0 + ty * 8 + i;
        if (gm >= M) continue;
#pragma unroll
        for (int j = 0; j < 8; j++) {
            int gn = col0 + tx * 8 + j;
            if (gn >= N) continue;
            float v = acc[i][j] * scale;
            if (EPI & EPI_BIAS)  v += bias[gn];
            if (EPI & EPI_RESID) v += resid[(long long)gm * ldc + gn];
            if (EPI & EPI_RELU)  v = fmaxf(v, 0.f);
            C[(long long)gm * ldc + gn] = v;
        }
    }
}

// ---------------- row softmax over scores (with mask) -----------------------
__global__ void __launch_bounds__(256)
softmax_k(float* __restrict__ scores, const int* __restrict__ mask)
{
    const long long row = blockIdx.x;                  // B*H*S rows
    float* p = scores + row * SS;
    const int b = (int)(row / ((long long)HEADS * SS));
    const int* mrow = mask + (long long)b * SS;
    const int tid = threadIdx.x;                        // 256 thr, 8 elems each

    float v[8];
    float mx = -3.0e38f;
#pragma unroll
    for (int i = 0; i < 8; i++) {
        int k = tid * 8 + i;
        float x = p[k];
        if (mrow[k] == 0) x = NEGV;
        v[i] = x;
        mx = fmaxf(mx, x);
    }
    __shared__ float red[256];
    red[tid] = mx; __syncthreads();
    for (int s = 128; s > 0; s >>= 1) {
        if (tid < s) red[tid] = fmaxf(red[tid], red[tid + s]);
        __syncthreads();
    }
    mx = red[0]; __syncthreads();

    float sum = 0.f;
#pragma unroll
    for (int i = 0; i < 8; i++) { v[i] = __expf(v[i] - mx); sum += v[i]; }
    red[tid] = sum; __syncthreads();
    for (int s = 128; s > 0; s >>= 1) {
        if (tid < s) red[tid] += red[tid + s];
        __syncthreads();
    }
    float inv = 1.0f / red[0];
#pragma unroll
    for (int i = 0; i < 8; i++) p[tid * 8 + i] = v[i] * inv;
}

// ---------------- LayerNorm (torch-from-scratch: ddof=1, /(std+eps)) --------
__global__ void __launch_bounds__(256)
ln_k(const float* __restrict__ in, float* __restrict__ out,
     const float* __restrict__ alpha, const float* __restrict__ beta)
{
    const long long row = blockIdx.x;
    const float* p = in + row * D_MODEL;
    float* o = out + row * D_MODEL;
    const int tid = threadIdx.x;                        // 256 thr, 4 elems each

    float x[4], s = 0.f, sq = 0.f;
#pragma unroll
    for (int i = 0; i < 4; i++) {
        x[i] = p[tid * 4 + i];
        s += x[i]; sq += x[i] * x[i];
    }
    __shared__ float rs[256], rq[256];
    rs[tid] = s; rq[tid] = sq; __syncthreads();
    for (int st = 128; st > 0; st >>= 1) {
        if (tid < st) { rs[tid] += rs[tid + st]; rq[tid] += rq[tid + st]; }
        __syncthreads();
    }
    float mean = rs[0] * (1.0f / D_MODEL);
    float var  = (rq[0] - rs[0] * mean) * (1.0f / (D_MODEL - 1));
    var = fmaxf(var, 0.f);
    float inv = 1.0f / (sqrtf(var) + LN_EPS);
#pragma unroll
    for (int i = 0; i < 4; i++) {
        int d = tid * 4 + i;
        o[d] = alpha[d] * (x[i] - mean) * inv + beta[d];
    }
}

// ---------------- launcher ---------------------------------------------------
extern "C" void kernel_launch(void* const* d_in, const int* in_sizes, int n_in,
                              void* d_out, int out_size)
{
    const float* x     = (const float*)d_in[0];
    const int*   mask  = (const int*)  d_in[1];
    const float* w_q   = (const float*)d_in[2];
    const float* w_k   = (const float*)d_in[3];
    const float* w_v   = (const float*)d_in[4];
    const float* w_o   = (const float*)d_in[5];
    const float* W1    = (const float*)d_in[6];
    const float* b1    = (const float*)d_in[7];
    const float* W2    = (const float*)d_in[8];
    const float* b2    = (const float*)d_in[9];
    const float* al1   = (const float*)d_in[10];
    const float* be1   = (const float*)d_in[11];
    const float* al2   = (const float*)d_in[12];
    const float* be2   = (const float*)d_in[13];
    float* out = (float*)d_out;

    float *Q, *Kb, *V, *SC, *CTX, *T1, *X1, *H, *T2;
    cudaGetSymbolAddress((void**)&Q,   g_Q);
    cudaGetSymbolAddress((void**)&Kb,  g_Kb);
    cudaGetSymbolAddress((void**)&V,   g_V);
    cudaGetSymbolAddress((void**)&SC,  g_sc);
    cudaGetSymbolAddress((void**)&CTX, g_ctx);
    cudaGetSymbolAddress((void**)&T1,  g_t1);
    cudaGetSymbolAddress((void**)&X1,  g_x1);
    cudaGetSymbolAddress((void**)&H,   g_h);
    cudaGetSymbolAddress((void**)&T2,  g_t2);

    const dim3 blk(256);
    auto grd = [](int N, int M, int z) {
        return dim3((unsigned)((N + 127) / 128), (unsigned)((M + 127) / 128), (unsigned)z);
    };
    const long long ZERO = 0;
    const long long sA   = (long long)SS * D_MODEL;    // per-batch stride in Q/K/V/ctx
    const long long sSC  = (long long)SS * SS;         // per-head stride in scores

    // 1-3: Q/K/V projections  [4096,1024] = x @ w
    sgemm_k<0,0><<<grd(D_MODEL, NTOK, 1), blk>>>(x, w_q, Q,  NTOK, D_MODEL, D_MODEL,
        D_MODEL, D_MODEL, D_MODEL, ZERO,ZERO,ZERO,ZERO,ZERO,ZERO, 1, 1.f, nullptr, nullptr);
    sgemm_k<0,0><<<grd(D_MODEL, NTOK, 1), blk>>>(x, w_k, Kb, NTOK, D_MODEL, D_MODEL,
        D_MODEL, D_MODEL, D_MODEL, ZERO,ZERO,ZERO,ZERO,ZERO,ZERO, 1, 1.f, nullptr, nullptr);
    sgemm_k<0,0><<<grd(D_MODEL, NTOK, 1), blk>>>(x, w_v, V,  NTOK, D_MODEL, D_MODEL,
        D_MODEL, D_MODEL, D_MODEL, ZERO,ZERO,ZERO,ZERO,ZERO,ZERO, 1, 1.f, nullptr, nullptr);

    // 4: scores[b,h] = Q_bh @ K_bh^T / 8     (32 batches of [2048x64]@[64x2048])
    sgemm_k<1,0><<<grd(SS, SS, BB * HEADS), blk>>>(Q, Kb, SC, SS, SS, DK,
        D_MODEL, D_MODEL, SS,
        (long long)DK, sA, (long long)DK, sA, sSC, (long long)HEADS * sSC,
        HEADS, 0.125f, nullptr, nullptr);

    // 5: masked softmax over key dim
    softmax_k<<<BB * HEADS * SS, blk>>>(SC, mask);

    // 6: ctx[b,h] = attn @ V_bh              (32 batches of [2048x2048]@[2048x64])
    sgemm_k<0,0><<<grd(DK, SS, BB * HEADS), blk>>>(SC, V, CTX, SS, DK, SS,
        SS, D_MODEL, D_MODEL,
        sSC, (long long)HEADS * sSC, (long long)DK, sA, (long long)DK, sA,
        HEADS, 1.f, nullptr, nullptr);

    // 7: t1 = ctx @ w_o + x  (residual)
    sgemm_k<0,EPI_RESID><<<grd(D_MODEL, NTOK, 1), blk>>>(CTX, w_o, T1, NTOK, D_MODEL, D_MODEL,
        D_MODEL, D_MODEL, D_MODEL, ZERO,ZERO,ZERO,ZERO,ZERO,ZERO, 1, 1.f, nullptr, x);

    // 8: x1 = LN1(t1)
    ln_k<<<NTOK, blk>>>(T1, X1, al1, be1);

    // 9: h = relu(x1 @ W1 + b1)
    sgemm_k<0,EPI_BIAS|EPI_RELU><<<grd(D_FF, NTOK, 1), blk>>>(X1, W1, H, NTOK, D_FF, D_MODEL,
        D_MODEL, D_FF, D_FF, ZERO,ZERO,ZERO,ZERO,ZERO,ZERO, 1, 1.f, b1, nullptr);

    // 10: t2 = h @ W2 + b2 + x1 (residual)
    sgemm_k<0,EPI_BIAS|EPI_RESID><<<grd(D_MODEL, NTOK, 1), blk>>>(H, W2, T2, NTOK, D_MODEL, D_FF,
        D_FF, D_MODEL, D_MODEL, ZERO,ZERO,ZERO,ZERO,ZERO,ZERO, 1, 1.f, b2, X1);

    // 11: out = LN2(t2)
    ln_k<<<NTOK, blk>>>(T2, out, al2, be2);
}

// round 2
// speedup vs baseline: 3.0234x; 3.0234x over previous
#include <cuda_runtime.h>
#include <cuda_bf16.h>
#include <cstdint>

#define D_MODEL 1024
#define HEADS   16
#define DK      64
#define D_FF    4096
#define BB      2
#define SS      2048
#define NTOK    (BB * SS)        // 4096
#define LN_EPS  1e-6f
#define NEGV    (-1e9f)

// ---------------- scratch (device globals; no runtime allocation) -----------
__device__ float g_Q  [NTOK * D_MODEL];
__device__ float g_Kb [NTOK * D_MODEL];
__device__ float g_V  [NTOK * D_MODEL];
__device__ float g_sc [134217728];          // B*H*S*S = 2*16*2048*2048 (512 MB)
__device__ float g_ctx[NTOK * D_MODEL];
__device__ float g_t1 [NTOK * D_MODEL];
__device__ float g_x1 [NTOK * D_MODEL];
__device__ float g_h  [NTOK * D_FF];
__device__ float g_t2 [NTOK * D_MODEL];

#define EPI_BIAS  1
#define EPI_RELU  2
#define EPI_RESID 4

__device__ __forceinline__ uint32_t f2tf32(float x) {
    uint32_t y;
    asm("cvt.rna.tf32.f32 %0, %1;" : "=r"(y) : "f"(x));
    return y;
}

__device__ __forceinline__ void mma_tf32(float& c0, float& c1, float& c2, float& c3,
                                         uint32_t a0, uint32_t a1, uint32_t a2, uint32_t a3,
                                         uint32_t b0, uint32_t b1) {
    asm volatile(
        "mma.sync.aligned.m16n8k8.row.col.f32.tf32.tf32.f32 "
        "{%0,%1,%2,%3}, {%4,%5,%6,%7}, {%8,%9}, {%0,%1,%2,%3};"
        : "+f"(c0), "+f"(c1), "+f"(c2), "+f"(c3)
        : "r"(a0), "r"(a1), "r"(a2), "r"(a3), "r"(b0), "r"(b1));
}

// ---------------- tf32 tensor-core batched GEMM ------------------------------
// C[m,n] = scale * sum_k A[m,k] * B(k,n)  (B row-major KxN, or NxK if TRANSB)
// Block tile 128x128x32, 8 warps of 64x32, m16n8k8 tf32 MMA, fp32 accumulate.
// Assumes M % 128 == 0, K % 32 == 0 (true for all call sites). N guarded.
template<int TRANSB, int EPI>
__global__ void __launch_bounds__(256)
tgemm_k(const float* __restrict__ A, const float* __restrict__ B,
        float* __restrict__ C, int M, int N, int K,
        int lda, int ldb, int ldc,
        long long offAh, long long offAb,
        long long offBh, long long offBb,
        long long offCh, long long offCb, int batchH,
        float scale, const float* __restrict__ bias,
        const float* __restrict__ resid)
{
    const int z  = blockIdx.z;
    const int bb = z / batchH, hh = z % batchH;
    A += bb * offAb + hh * offAh;
    B += bb * offBb + hh * offBh;
    C += bb * offCb + hh * offCh;

    // A smem: [m][k] 128 x 32, stride 36 (bank = 4m+k : conflict-free frag loads)
    // B smem: TRANSB -> [n][k] 128 x 32 stride 36 ; else [k][n] 32 x 128 stride 136
    __shared__ float As[128 * 36];
    __shared__ float Bs[TRANSB ? 128 * 36 : 32 * 136];

    const int tid  = threadIdx.x;
    const int lane = tid & 31;
    const int wid  = tid >> 5;
    const int wm   = wid >> 2;      // 0..1  (warp m)
    const int wn   = wid & 3;       // 0..3  (warp n)
    const int gid  = lane >> 2;     // 0..7
    const int tig  = lane & 3;      // 0..3

    const int row0 = blockIdx.y * 128;
    const int col0 = blockIdx.x * 128;

    float acc[4][4][4];
#pragma unroll
    for (int mi = 0; mi < 4; mi++)
#pragma unroll
        for (int ni = 0; ni < 4; ni++)
#pragma unroll
            for (int r = 0; r < 4; r++) acc[mi][ni][r] = 0.f;

    // staging index precompute
    int amf[4], akv[4];
#pragma unroll
    for (int i = 0; i < 4; i++) {
        int f = tid + i * 256;      // float4 index, 0..1023
        amf[i] = f >> 3;            // m row 0..127
        akv[i] = (f & 7) * 4;       // k 0..28
    }
    int bkf[4], bnv[4];             // for non-trans B tile (32 x 128)
#pragma unroll
    for (int i = 0; i < 4; i++) {
        int f = tid + i * 256;
        bkf[i] = f >> 5;            // k row 0..31
        bnv[i] = (f & 31) * 4;      // n 0..124
    }

    const int nkt = K >> 5;         // K / 32
    float4 ra[4], rb[4];

    // ---- load tile kt into staging regs ----
    auto loadA = [&](int kt) {
        const int k0 = kt * 32;
#pragma unroll
        for (int i = 0; i < 4; i++)
            ra[i] = *(const float4*)&A[(long long)(row0 + amf[i]) * lda + k0 + akv[i]];
    };
    auto loadB = [&](int kt) {
        const int k0 = kt * 32;
        if (TRANSB) {
#pragma unroll
            for (int i = 0; i < 4; i++)
                rb[i] = *(const float4*)&B[(long long)(col0 + amf[i]) * ldb + k0 + akv[i]];
        } else {
#pragma unroll
            for (int i = 0; i < 4; i++) {
                int gn = col0 + bnv[i];
                rb[i] = (gn < N) ? *(const float4*)&B[(long long)(k0 + bkf[i]) * ldb + gn]
                                 : make_float4(0.f, 0.f, 0.f, 0.f);
            }
        }
    };
    auto storeA = [&]() {
#pragma unroll
        for (int i = 0; i < 4; i++) {
            float4 v = ra[i];
            v.x = __uint_as_float(f2tf32(v.x));
            v.y = __uint_as_float(f2tf32(v.y));
            v.z = __uint_as_float(f2tf32(v.z));
            v.w = __uint_as_float(f2tf32(v.w));
            *(float4*)&As[amf[i] * 36 + akv[i]] = v;
        }
    };
    auto storeB = [&]() {
#pragma unroll
        for (int i = 0; i < 4; i++) {
            float4 v = rb[i];
            v.x = __uint_as_float(f2tf32(v.x));
            v.y = __uint_as_float(f2tf32(v.y));
            v.z = __uint_as_float(f2tf32(v.z));
            v.w = __uint_as_float(f2tf32(v.w));
            if (TRANSB) *(float4*)&Bs[amf[i] * 36 + akv[i]] = v;
            else        *(float4*)&Bs[bkf[i] * 136 + bnv[i]] = v;
        }
    };

    loadA(0); loadB(0);
    storeA(); storeB();
    __syncthreads();

    const uint32_t* Asu = (const uint32_t*)As;
    const uint32_t* Bsu = (const uint32_t*)Bs;

    for (int kt = 0; kt < nkt; kt++) {
        if (kt + 1 < nkt) { loadA(kt + 1); loadB(kt + 1); }

#pragma unroll
        for (int ks = 0; ks < 4; ks++) {
            const int k = ks * 8;
            uint32_t af[4][4], bf[4][2];
#pragma unroll
            for (int mi = 0; mi < 4; mi++) {
                int m = wm * 64 + mi * 16 + gid;
                af[mi][0] = Asu[m * 36 + k + tig];
                af[mi][1] = Asu[(m + 8) * 36 + k + tig];
                af[mi][2] = Asu[m * 36 + k + tig + 4];
                af[mi][3] = Asu[(m + 8) * 36 + k + tig + 4];
            }
#pragma unroll
            for (int ni = 0; ni < 4; ni++) {
                int n = wn * 32 + ni * 8 + gid;
                if (TRANSB) {
                    bf[ni][0] = Bsu[n * 36 + k + tig];
                    bf[ni][1] = Bsu[n * 36 + k + tig + 4];
                } else {
                    bf[ni][0] = Bsu[(k + tig) * 136 + n];
                    bf[ni][1] = Bsu[(k + tig + 4) * 136 + n];
                }
            }
#pragma unroll
            for (int mi = 0; mi < 4; mi++)
#pragma unroll
                for (int ni = 0; ni < 4; ni++)
                    mma_tf32(acc[mi][ni][0], acc[mi][ni][1], acc[mi][ni][2], acc[mi][ni][3],
                             af[mi][0], af[mi][1], af[mi][2], af[mi][3],
                             bf[ni][0], bf[ni][1]);
        }
        __syncthreads();
        if (kt + 1 < nkt) { storeA(); storeB(); __syncthreads(); }
    }

    // ---- epilogue ----
#pragma unroll
    for (int mi = 0; mi < 4; mi++) {
#pragma unroll
        for (int ni = 0; ni < 4; ni++) {
            int r0 = row0 + wm * 64 + mi * 16 + gid;
            int cb = col0 + wn * 32 + ni * 8 + tig * 2;
            if (cb >= N) continue;
#pragma unroll
            for (int half = 0; half < 2; half++) {
                int rr = r0 + half * 8;
                float v0 = acc[mi][ni][half * 2 + 0] * scale;
                float v1 = acc[mi][ni][half * 2 + 1] * scale;
                if (EPI & EPI_BIAS)  { v0 += bias[cb]; v1 += bias[cb + 1]; }
                if (EPI & EPI_RESID) {
                    const float2 rv = *(const float2*)&resid[(long long)rr * ldc + cb];
                    v0 += rv.x; v1 += rv.y;
                }
                if (EPI & EPI_RELU)  { v0 = fmaxf(v0, 0.f); v1 = fmaxf(v1, 0.f); }
                *(float2*)&C[(long long)rr * ldc + cb] = make_float2(v0, v1);
            }
        }
    }
}

// ---------------- row softmax over scores (with mask) -----------------------
__global__ void __launch_bounds__(256)
softmax_k(float* __restrict__ scores, const int* __restrict__ mask)
{
    const long long row = blockIdx.x;                  // B*H*S rows
    float* p = scores + row * SS;
    const int b = (int)(row / ((long long)HEADS * SS));
    const int* mrow = mask + (long long)b * SS;
    const int tid = threadIdx.x;                        // 256 thr, 8 elems each

    float v[8];
    float mx = -3.0e38f;
#pragma unroll
    for (int j = 0; j < 2; j++) {
        float4 x4 = ((const float4*)p)[tid * 2 + j];
        int4   m4 = ((const int4*)mrow)[tid * 2 + j];
        v[j*4+0] = (m4.x == 0) ? NEGV : x4.x;
        v[j*4+1] = (m4.y == 0) ? NEGV : x4.y;
        v[j*4+2] = (m4.z == 0) ? NEGV : x4.z;
        v[j*4+3] = (m4.w == 0) ? NEGV : x4.w;
    }
#pragma unroll
    for (int i = 0; i < 8; i++) mx = fmaxf(mx, v[i]);

    __shared__ float red[256];
    red[tid] = mx; __syncthreads();
    for (int s = 128; s > 0; s >>= 1) {
        if (tid < s) red[tid] = fmaxf(red[tid], red[tid + s]);
        __syncthreads();
    }
    mx = red[0]; __syncthreads();

    float sum = 0.f;
#pragma unroll
    for (int i = 0; i < 8; i++) { v[i] = __expf(v[i] - mx); sum += v[i]; }
    red[tid] = sum; __syncthreads();
    for (int s = 128; s > 0; s >>= 1) {
        if (tid < s) red[tid] += red[tid + s];
        __syncthreads();
    }
    float inv = 1.0f / red[0];
#pragma unroll
    for (int j = 0; j < 2; j++) {
        float4 o;
        o.x = v[j*4+0] * inv; o.y = v[j*4+1] * inv;
        o.z = v[j*4+2] * inv; o.w = v[j*4+3] * inv;
        ((float4*)p)[tid * 2 + j] = o;
    }
}

// ---------------- LayerNorm (torch-from-scratch: ddof=1, /(std+eps)) --------
__global__ void __launch_bounds__(256)
ln_k(const float* __restrict__ in, float* __restrict__ out,
     const float* __restrict__ alpha, const float* __restrict__ beta)
{
    const long long row = blockIdx.x;
    const float* p = in + row * D_MODEL;
    float* o = out + row * D_MODEL;
    const int tid = threadIdx.x;                        // 256 thr, 4 elems each

    float4 x4 = ((const float4*)p)[tid];
    float s  = x4.x + x4.y + x4.z + x4.w;
    float sq = x4.x*x4.x + x4.y*x4.y + x4.z*x4.z + x4.w*x4.w;

    __shared__ float rs[256], rq[256];
    rs[tid] = s; rq[tid] = sq; __syncthreads();
    for (int st = 128; st > 0; st >>= 1) {
        if (tid < st) { rs[tid] += rs[tid + st]; rq[tid] += rq[tid + st]; }
        __syncthreads();
    }
    float mean = rs[0] * (1.0f / D_MODEL);
    float var  = (rq[0] - rs[0] * mean) * (1.0f / (D_MODEL - 1));
    var = fmaxf(var, 0.f);
    float inv = 1.0f / (sqrtf(var) + LN_EPS);

    float4 a4 = ((const float4*)alpha)[tid];
    float4 b4 = ((const float4*)beta)[tid];
    float4 o4;
    o4.x = a4.x * (x4.x - mean) * inv + b4.x;
    o4.y = a4.y * (x4.y - mean) * inv + b4.y;
    o4.z = a4.z * (x4.z - mean) * inv + b4.z;
    o4.w = a4.w * (x4.w - mean) * inv + b4.w;
    ((float4*)o)[tid] = o4;
}

// ---------------- launcher ---------------------------------------------------
extern "C" void kernel_launch(void* const* d_in, const int* in_sizes, int n_in,
                              void* d_out, int out_size)
{
    const float* x     = (const float*)d_in[0];
    const int*   mask  = (const int*)  d_in[1];
    const float* w_q   = (const float*)d_in[2];
    const float* w_k   = (const float*)d_in[3];
    const float* w_v   = (const float*)d_in[4];
    const float* w_o   = (const float*)d_in[5];
    const float* W1    = (const float*)d_in[6];
    const float* b1    = (const float*)d_in[7];
    const float* W2    = (const float*)d_in[8];
    const float* b2    = (const float*)d_in[9];
    const float* al1   = (const float*)d_in[10];
    const float* be1   = (const float*)d_in[11];
    const float* al2   = (const float*)d_in[12];
    const float* be2   = (const float*)d_in[13];
    float* out = (float*)d_out;

    float *Q, *Kb, *V, *SC, *CTX, *T1, *X1, *H, *T2;
    cudaGetSymbolAddress((void**)&Q,   g_Q);
    cudaGetSymbolAddress((void**)&Kb,  g_Kb);
    cudaGetSymbolAddress((void**)&V,   g_V);
    cudaGetSymbolAddress((void**)&SC,  g_sc);
    cudaGetSymbolAddress((void**)&CTX, g_ctx);
    cudaGetSymbolAddress((void**)&T1,  g_t1);
    cudaGetSymbolAddress((void**)&X1,  g_x1);
    cudaGetSymbolAddress((void**)&H,   g_h);
    cudaGetSymbolAddress((void**)&T2,  g_t2);

    const dim3 blk(256);
    auto grd = [](int N, int M, int z) {
        return dim3((unsigned)((N + 127) / 128), (unsigned)((M + 127) / 128), (unsigned)z);
    };
    const long long ZERO = 0;
    const long long sA   = (long long)SS * D_MODEL;    // per-batch stride in Q/K/V/ctx
    const long long sSC  = (long long)SS * SS;         // per-head stride in scores

    // 1-3: Q/K/V projections  [4096,1024] = x @ w
    tgemm_k<0,0><<<grd(D_MODEL, NTOK, 1), blk>>>(x, w_q, Q,  NTOK, D_MODEL, D_MODEL,
        D_MODEL, D_MODEL, D_MODEL, ZERO,ZERO,ZERO,ZERO,ZERO,ZERO, 1, 1.f, nullptr, nullptr);
    tgemm_k<0,0><<<grd(D_MODEL, NTOK, 1), blk>>>(x, w_k, Kb, NTOK, D_MODEL, D_MODEL,
        D_MODEL, D_MODEL, D_MODEL, ZERO,ZERO,ZERO,ZERO,ZERO,ZERO, 1, 1.f, nullptr, nullptr);
    tgemm_k<0,0><<<grd(D_MODEL, NTOK, 1), blk>>>(x, w_v, V,  NTOK, D_MODEL, D_MODEL,
        D_MODEL, D_MODEL, D_MODEL, ZERO,ZERO,ZERO,ZERO,ZERO,ZERO, 1, 1.f, nullptr, nullptr);

    // 4: scores[b,h] = Q_bh @ K_bh^T / 8     (32 batches of [2048x64]@[64x2048])
    tgemm_k<1,0><<<grd(SS, SS, BB * HEADS), blk>>>(Q, Kb, SC, SS, SS, DK,
        D_MODEL, D_MODEL, SS,
        (long long)DK, sA, (long long)DK, sA, sSC, (long long)HEADS * sSC,
        HEADS, 0.125f, nullptr, nullptr);

    // 5: masked softmax over key dim
    softmax_k<<<BB * HEADS * SS, blk>>>(SC, mask);

    // 6: ctx[b,h] = attn @ V_bh              (32 batches of [2048x2048]@[2048x64])
    tgemm_k<0,0><<<grd(DK, SS, BB * HEADS), blk>>>(SC, V, CTX, SS, DK, SS,
        SS, D_MODEL, D_MODEL,
        sSC, (long long)HEADS * sSC, (long long)DK, sA, (long long)DK, sA,
        HEADS, 1.f, nullptr, nullptr);

    // 7: t1 = ctx @ w_o + x  (residual)
    tgemm_k<0,EPI_RESID><<<grd(D_MODEL, NTOK, 1), blk>>>(CTX, w_o, T1, NTOK, D_MODEL, D_MODEL,
        D_MODEL, D_MODEL, D_MODEL, ZERO,ZERO,ZERO,ZERO,ZERO,ZERO, 1, 1.f, nullptr, x);

    // 8: x1 = LN1(t1)
    ln_k<<<NTOK, blk>>>(T1, X1, al1, be1);

    // 9: h = relu(x1 @ W1 + b1)
    tgemm_k<0,EPI_BIAS|EPI_RELU><<<grd(D_FF, NTOK, 1), blk>>>(X1, W1, H, NTOK, D_FF, D_MODEL,
        D_MODEL, D_FF, D_FF, ZERO,ZERO,ZERO,ZERO,ZERO,ZERO, 1, 1.f, b1, nullptr);

    // 10: t2 = h @ W2 + b2 + x1 (residual)
    tgemm_k<0,EPI_BIAS|EPI_RESID><<<grd(D_MODEL, NTOK, 1), blk>>>(H, W2, T2, NTOK, D_MODEL, D_FF,
        D_FF, D_MODEL, D_MODEL, ZERO,ZERO,ZERO,ZERO,ZERO,ZERO, 1, 1.f, b2, X1);

    // 11: out = LN2(t2)
    ln_k<<<NTOK, blk>>>(T2, out, al2, be2);
}

// round 3
// speedup vs baseline: 3.9952x; 1.3214x over previous
#include <cuda_runtime.h>
#include <cuda_bf16.h>
#include <cstdint>

#define D_MODEL 1024
#define HEADS   16
#define DK      64
#define D_FF    4096
#define BB      2
#define SS      2048
#define NTOK    (BB * SS)        // 4096
#define LN_EPS  1e-6f
#define NEGV    (-1e9f)

// ---------------- scratch (device globals; no runtime allocation) -----------
__device__ float g_Q  [NTOK * D_MODEL];
__device__ float g_Kb [NTOK * D_MODEL];
__device__ float g_V  [NTOK * D_MODEL];
__device__ float g_ctx[NTOK * D_MODEL];
__device__ float g_t1 [NTOK * D_MODEL];
__device__ float g_x1 [NTOK * D_MODEL];
__device__ float g_h  [NTOK * D_FF];
__device__ float g_t2 [NTOK * D_MODEL];

#define EPI_BIAS  1
#define EPI_RELU  2
#define EPI_RESID 4

__device__ __forceinline__ uint32_t f2tf32(float x) {
    uint32_t y;
    asm("cvt.rna.tf32.f32 %0, %1;" : "=r"(y) : "f"(x));
    return y;
}

__device__ __forceinline__ void mma_tf32(float& c0, float& c1, float& c2, float& c3,
                                         uint32_t a0, uint32_t a1, uint32_t a2, uint32_t a3,
                                         uint32_t b0, uint32_t b1) {
    asm volatile(
        "mma.sync.aligned.m16n8k8.row.col.f32.tf32.tf32.f32 "
        "{%0,%1,%2,%3}, {%4,%5,%6,%7}, {%8,%9}, {%0,%1,%2,%3};"
        : "+f"(c0), "+f"(c1), "+f"(c2), "+f"(c3)
        : "r"(a0), "r"(a1), "r"(a2), "r"(a3), "r"(b0), "r"(b1));
}

// ---------------- tf32 tensor-core batched GEMM ------------------------------
template<int TRANSB, int EPI>
__global__ void __launch_bounds__(256)
tgemm_k(const float* __restrict__ A, const float* __restrict__ B,
        float* __restrict__ C, int M, int N, int K,
        int lda, int ldb, int ldc,
        float scale, const float* __restrict__ bias,
        const float* __restrict__ resid)
{
    __shared__ float As[128 * 36];
    __shared__ float Bs[TRANSB ? 128 * 36 : 32 * 136];

    const int tid  = threadIdx.x;
    const int lane = tid & 31;
    const int wid  = tid >> 5;
    const int wm   = wid >> 2;
    const int wn   = wid & 3;
    const int gid  = lane >> 2;
    const int tig  = lane & 3;

    const int row0 = blockIdx.y * 128;
    const int col0 = blockIdx.x * 128;

    float acc[4][4][4];
#pragma unroll
    for (int mi = 0; mi < 4; mi++)
#pragma unroll
        for (int ni = 0; ni < 4; ni++)
#pragma unroll
            for (int r = 0; r < 4; r++) acc[mi][ni][r] = 0.f;

    int amf[4], akv[4], bkf[4], bnv[4];
#pragma unroll
    for (int i = 0; i < 4; i++) {
        int f = tid + i * 256;
        amf[i] = f >> 3;   akv[i] = (f & 7) * 4;
        bkf[i] = f >> 5;   bnv[i] = (f & 31) * 4;
    }

    const int nkt = K >> 5;
    float4 ra[4], rb[4];

    auto loadA = [&](int kt) {
        const int k0 = kt * 32;
#pragma unroll
        for (int i = 0; i < 4; i++)
            ra[i] = *(const float4*)&A[(long long)(row0 + amf[i]) * lda + k0 + akv[i]];
    };
    auto loadB = [&](int kt) {
        const int k0 = kt * 32;
        if (TRANSB) {
#pragma unroll
            for (int i = 0; i < 4; i++)
                rb[i] = *(const float4*)&B[(long long)(col0 + amf[i]) * ldb + k0 + akv[i]];
        } else {
#pragma unroll
            for (int i = 0; i < 4; i++) {
                int gn = col0 + bnv[i];
                rb[i] = (gn < N) ? *(const float4*)&B[(long long)(k0 + bkf[i]) * ldb + gn]
                                 : make_float4(0.f, 0.f, 0.f, 0.f);
            }
        }
    };
    auto storeA = [&]() {
#pragma unroll
        for (int i = 0; i < 4; i++) {
            float4 v = ra[i];
            v.x = __uint_as_float(f2tf32(v.x));
            v.y = __uint_as_float(f2tf32(v.y));
            v.z = __uint_as_float(f2tf32(v.z));
            v.w = __uint_as_float(f2tf32(v.w));
            *(float4*)&As[amf[i] * 36 + akv[i]] = v;
        }
    };
    auto storeB = [&]() {
#pragma unroll
        for (int i = 0; i < 4; i++) {
            float4 v = rb[i];
            v.x = __uint_as_float(f2tf32(v.x));
            v.y = __uint_as_float(f2tf32(v.y));
            v.z = __uint_as_float(f2tf32(v.z));
            v.w = __uint_as_float(f2tf32(v.w));
            if (TRANSB) *(float4*)&Bs[amf[i] * 36 + akv[i]] = v;
            else        *(float4*)&Bs[bkf[i] * 136 + bnv[i]] = v;
        }
    };

    loadA(0); loadB(0);
    storeA(); storeB();
    __syncthreads();

    const uint32_t* Asu = (const uint32_t*)As;
    const uint32_t* Bsu = (const uint32_t*)Bs;

    for (int kt = 0; kt < nkt; kt++) {
        if (kt + 1 < nkt) { loadA(kt + 1); loadB(kt + 1); }

#pragma unroll
        for (int ks = 0; ks < 4; ks++) {
            const int k = ks * 8;
            uint32_t af[4][4], bf[4][2];
#pragma unroll
            for (int mi = 0; mi < 4; mi++) {
                int m = wm * 64 + mi * 16 + gid;
                af[mi][0] = Asu[m * 36 + k + tig];
                af[mi][1] = Asu[(m + 8) * 36 + k + tig];
                af[mi][2] = Asu[m * 36 + k + tig + 4];
                af[mi][3] = Asu[(m + 8) * 36 + k + tig + 4];
            }
#pragma unroll
            for (int ni = 0; ni < 4; ni++) {
                int n = wn * 32 + ni * 8 + gid;
                if (TRANSB) {
                    bf[ni][0] = Bsu[n * 36 + k + tig];
                    bf[ni][1] = Bsu[n * 36 + k + tig + 4];
                } else {
                    bf[ni][0] = Bsu[(k + tig) * 136 + n];
                    bf[ni][1] = Bsu[(k + tig + 4) * 136 + n];
                }
            }
#pragma unroll
            for (int mi = 0; mi < 4; mi++)
#pragma unroll
                for (int ni = 0; ni < 4; ni++)
                    mma_tf32(acc[mi][ni][0], acc[mi][ni][1], acc[mi][ni][2], acc[mi][ni][3],
                             af[mi][0], af[mi][1], af[mi][2], af[mi][3],
                             bf[ni][0], bf[ni][1]);
        }
        __syncthreads();
        if (kt + 1 < nkt) { storeA(); storeB(); __syncthreads(); }
    }

#pragma unroll
    for (int mi = 0; mi < 4; mi++) {
#pragma unroll
        for (int ni = 0; ni < 4; ni++) {
            int r0 = row0 + wm * 64 + mi * 16 + gid;
            int cb = col0 + wn * 32 + ni * 8 + tig * 2;
            if (cb >= N) continue;
#pragma unroll
            for (int half = 0; half < 2; half++) {
                int rr = r0 + half * 8;
                float v0 = acc[mi][ni][half * 2 + 0] * scale;
                float v1 = acc[mi][ni][half * 2 + 1] * scale;
                if (EPI & EPI_BIAS)  { v0 += bias[cb]; v1 += bias[cb + 1]; }
                if (EPI & EPI_RESID) {
                    const float2 rv = *(const float2*)&resid[(long long)rr * ldc + cb];
                    v0 += rv.x; v1 += rv.y;
                }
                if (EPI & EPI_RELU)  { v0 = fmaxf(v0, 0.f); v1 = fmaxf(v1, 0.f); }
                *(float2*)&C[(long long)rr * ldc + cb] = make_float2(v0, v1);
            }
        }
    }
}

// ---------------- fused flash attention --------------------------------------
// CTA: 128 queries of one (b,h). 8 warps x 16 query rows. KV tiles of 64 keys.
// Smem floats: Qs 128x68 | Ks 64x68 | Vs 64x72 | Ps 128x68 | mask 64 ints.
#define FA_SMEM ((128*68 + 64*68 + 64*72 + 128*68) * 4 + 256)

__global__ void __launch_bounds__(256, 2)
fa_k(const float* __restrict__ Q, const float* __restrict__ K,
     const float* __restrict__ V, const int* __restrict__ mask,
     float* __restrict__ O)
{
    extern __shared__ float sm[];
    float* Qs = sm;                         // 128*68
    float* Ks = Qs + 128 * 68;              // 64*68
    float* Vs = Ks + 64 * 68;               // 64*72
    float* Ps = Vs + 64 * 72;               // 128*68
    int*   Ms = (int*)(Ps + 128 * 68);      // 64

    const int qt  = blockIdx.x;             // 0..15
    const int z   = blockIdx.y;             // 0..31
    const int b   = z >> 4, h = z & 15;
    const int tid = threadIdx.x, lane = tid & 31, w = tid >> 5;
    const int gid = lane >> 2, tig = lane & 3;

    const long long base = ((long long)b * SS) * D_MODEL + h * DK;
    const float* Qg = Q + base + (long long)qt * 128 * D_MODEL;
    const float* Kg = K + base;
    const float* Vg = V + base;
    const int*   mg = mask + (long long)b * SS;

    // ---- load Q tile (pre-scaled by 1/sqrt(dk)=0.125, tf32) ----
#pragma unroll
    for (int i = 0; i < 8; i++) {
        int idx = tid + i * 256;            // 0..2047
        int r = idx >> 4, c = (idx & 15) * 4;
        float4 v = *(const float4*)&Qg[(long long)r * D_MODEL + c];
        v.x = __uint_as_float(f2tf32(v.x * 0.125f));
        v.y = __uint_as_float(f2tf32(v.y * 0.125f));
        v.z = __uint_as_float(f2tf32(v.z * 0.125f));
        v.w = __uint_as_float(f2tf32(v.w * 0.125f));
        *(float4*)&Qs[r * 68 + c] = v;
    }

    float m0 = -INFINITY, m1 = -INFINITY;
    float l0 = 0.f, l1 = 0.f;
    float oacc[8][4];
#pragma unroll
    for (int ng = 0; ng < 8; ng++)
#pragma unroll
        for (int r = 0; r < 4; r++) oacc[ng][r] = 0.f;

    const uint32_t* Qsu = (const uint32_t*)Qs;
    const uint32_t* Ksu = (const uint32_t*)Ks;
    const uint32_t* Vsu = (const uint32_t*)Vs;
    const uint32_t* Psu = (const uint32_t*)Ps;
    const int qrow = w * 16 + gid;          // my base query row in tile

    for (int kt = 0; kt < SS / 64; kt++) {
        __syncthreads();                    // prev tile fully consumed (and Qs visible at kt=0)
        // ---- load K/V tile (64 keys x 64 dims), tf32 ----
#pragma unroll
        for (int i = 0; i < 4; i++) {
            int idx = tid + i * 256;        // 0..1023
            int r = idx >> 4, c = (idx & 15) * 4;
            long long go = (long long)(kt * 64 + r) * D_MODEL + c;
            float4 kv = *(const float4*)&Kg[go];
            kv.x = __uint_as_float(f2tf32(kv.x));
            kv.y = __uint_as_float(f2tf32(kv.y));
            kv.z = __uint_as_float(f2tf32(kv.z));
            kv.w = __uint_as_float(f2tf32(kv.w));
            *(float4*)&Ks[r * 68 + c] = kv;
            float4 vv = *(const float4*)&Vg[go];
            vv.x = __uint_as_float(f2tf32(vv.x));
            vv.y = __uint_as_float(f2tf32(vv.y));
            vv.z = __uint_as_float(f2tf32(vv.z));
            vv.w = __uint_as_float(f2tf32(vv.w));
            *(float4*)&Vs[r * 72 + c] = vv;
        }
        if (tid < 64) Ms[tid] = mg[kt * 64 + tid];
        __syncthreads();

        // ---- S = Qs @ Ks^T : per warp m16 x n64, k64 ----
        float s[8][4];
#pragma unroll
        for (int ni = 0; ni < 8; ni++)
#pragma unroll
            for (int r = 0; r < 4; r++) s[ni][r] = 0.f;

#pragma unroll
        for (int kg = 0; kg < 8; kg++) {
            const int k = kg * 8;
            uint32_t a0 = Qsu[qrow * 68 + k + tig];
            uint32_t a1 = Qsu[(qrow + 8) * 68 + k + tig];
            uint32_t a2 = Qsu[qrow * 68 + k + tig + 4];
            uint32_t a3 = Qsu[(qrow + 8) * 68 + k + tig + 4];
#pragma unroll
            for (int ni = 0; ni < 8; ni++) {
                uint32_t b0 = Ksu[(ni * 8 + gid) * 68 + k + tig];
                uint32_t b1 = Ksu[(ni * 8 + gid) * 68 + k + tig + 4];
                mma_tf32(s[ni][0], s[ni][1], s[ni][2], s[ni][3], a0, a1, a2, a3, b0, b1);
            }
        }

        // ---- mask + tile row max ----
        float tm0 = -3.0e38f, tm1 = -3.0e38f;
#pragma unroll
        for (int ni = 0; ni < 8; ni++) {
            int c0 = ni * 8 + tig * 2;
            if (Ms[c0] == 0)     { s[ni][0] = NEGV; s[ni][2] = NEGV; }
            if (Ms[c0 + 1] == 0) { s[ni][1] = NEGV; s[ni][3] = NEGV; }
            tm0 = fmaxf(tm0, fmaxf(s[ni][0], s[ni][1]));
            tm1 = fmaxf(tm1, fmaxf(s[ni][2], s[ni][3]));
        }
        tm0 = fmaxf(tm0, __shfl_xor_sync(0xffffffffu, tm0, 1));
        tm0 = fmaxf(tm0, __shfl_xor_sync(0xffffffffu, tm0, 2));
        tm1 = fmaxf(tm1, __shfl_xor_sync(0xffffffffu, tm1, 1));
        tm1 = fmaxf(tm1, __shfl_xor_sync(0xffffffffu, tm1, 2));

        float mn0 = fmaxf(m0, tm0), mn1 = fmaxf(m1, tm1);
        float cr0 = __expf(m0 - mn0), cr1 = __expf(m1 - mn1);

        // ---- exp + row sums + write P (warp-private rows) ----
        float sum0 = 0.f, sum1 = 0.f;
#pragma unroll
        for (int ni = 0; ni < 8; ni++) {
            float p0 = __expf(s[ni][0] - mn0);
            float p1 = __expf(s[ni][1] - mn0);
            float p2 = __expf(s[ni][2] - mn1);
            float p3 = __expf(s[ni][3] - mn1);
            sum0 += p0 + p1; sum1 += p2 + p3;
            float2 lo, hi;
            lo.x = __uint_as_float(f2tf32(p0)); lo.y = __uint_as_float(f2tf32(p1));
            hi.x = __uint_as_float(f2tf32(p2)); hi.y = __uint_as_float(f2tf32(p3));
            *(float2*)&Ps[qrow * 68 + ni * 8 + tig * 2] = lo;
            *(float2*)&Ps[(qrow + 8) * 68 + ni * 8 + tig * 2] = hi;
        }
        sum0 += __shfl_xor_sync(0xffffffffu, sum0, 1);
        sum0 += __shfl_xor_sync(0xffffffffu, sum0, 2);
        sum1 += __shfl_xor_sync(0xffffffffu, sum1, 1);
        sum1 += __shfl_xor_sync(0xffffffffu, sum1, 2);

        l0 = l0 * cr0 + sum0;
        l1 = l1 * cr1 + sum1;
        m0 = mn0; m1 = mn1;

#pragma unroll
        for (int ng = 0; ng < 8; ng++) {
            oacc[ng][0] *= cr0; oacc[ng][1] *= cr0;
            oacc[ng][2] *= cr1; oacc[ng][3] *= cr1;
        }
        __syncwarp();

        // ---- O += P @ V : m16 x n64, k64 ----
#pragma unroll
        for (int kg = 0; kg < 8; kg++) {
            const int k = kg * 8;
            uint32_t a0 = Psu[qrow * 68 + k + tig];
            uint32_t a1 = Psu[(qrow + 8) * 68 + k + tig];
            uint32_t a2 = Psu[qrow * 68 + k + tig + 4];
            uint32_t a3 = Psu[(qrow + 8) * 68 + k + tig + 4];
#pragma unroll
            for (int ng = 0; ng < 8; ng++) {
                uint32_t b0 = Vsu[(k + tig) * 72 + ng * 8 + gid];
                uint32_t b1 = Vsu[(k + tig + 4) * 72 + ng * 8 + gid];
                mma_tf32(oacc[ng][0], oacc[ng][1], oacc[ng][2], oacc[ng][3],
                         a0, a1, a2, a3, b0, b1);
            }
        }
    }

    // ---- normalize & write ctx [tokens, D_MODEL] ----
    float inv0 = 1.0f / l0, inv1 = 1.0f / l1;
    float* Og = O + base + (long long)qt * 128 * D_MODEL;
#pragma unroll
    for (int ng = 0; ng < 8; ng++) {
        int c = ng * 8 + tig * 2;
        *(float2*)&Og[(long long)qrow * D_MODEL + c] =
            make_float2(oacc[ng][0] * inv0, oacc[ng][1] * inv0);
        *(float2*)&Og[(long long)(qrow + 8) * D_MODEL + c] =
            make_float2(oacc[ng][2] * inv1, oacc[ng][3] * inv1);
    }
}

// ---------------- LayerNorm (torch-from-scratch: ddof=1, /(std+eps)) --------
__global__ void __launch_bounds__(256)
ln_k(const float* __restrict__ in, float* __restrict__ out,
     const float* __restrict__ alpha, const float* __restrict__ beta)
{
    const long long row = blockIdx.x;
    const float* p = in + row * D_MODEL;
    float* o = out + row * D_MODEL;
    const int tid = threadIdx.x;

    float4 x4 = ((const float4*)p)[tid];
    float s  = x4.x + x4.y + x4.z + x4.w;
    float sq = x4.x*x4.x + x4.y*x4.y + x4.z*x4.z + x4.w*x4.w;

    __shared__ float rs[256], rq[256];
    rs[tid] = s; rq[tid] = sq; __syncthreads();
    for (int st = 128; st > 0; st >>= 1) {
        if (tid < st) { rs[tid] += rs[tid + st]; rq[tid] += rq[tid + st]; }
        __syncthreads();
    }
    float mean = rs[0] * (1.0f / D_MODEL);
    float var  = (rq[0] - rs[0] * mean) * (1.0f / (D_MODEL - 1));
    var = fmaxf(var, 0.f);
    float inv = 1.0f / (sqrtf(var) + LN_EPS);

    float4 a4 = ((const float4*)alpha)[tid];
    float4 b4 = ((const float4*)beta)[tid];
    float4 o4;
    o4.x = a4.x * (x4.x - mean) * inv + b4.x;
    o4.y = a4.y * (x4.y - mean) * inv + b4.y;
    o4.z = a4.z * (x4.z - mean) * inv + b4.z;
    o4.w = a4.w * (x4.w - mean) * inv + b4.w;
    ((float4*)o)[tid] = o4;
}

// ---------------- launcher ---------------------------------------------------
extern "C" void kernel_launch(void* const* d_in, const int* in_sizes, int n_in,
                              void* d_out, int out_size)
{
    const float* x     = (const float*)d_in[0];
    const int*   mask  = (const int*)  d_in[1];
    const float* w_q   = (const float*)d_in[2];
    const float* w_k   = (const float*)d_in[3];
    const float* w_v   = (const float*)d_in[4];
    const float* w_o   = (const float*)d_in[5];
    const float* W1    = (const float*)d_in[6];
    const float* b1    = (const float*)d_in[7];
    const float* W2    = (const float*)d_in[8];
    const float* b2    = (const float*)d_in[9];
    const float* al1   = (const float*)d_in[10];
    const float* be1   = (const float*)d_in[11];
    const float* al2   = (const float*)d_in[12];
    const float* be2   = (const float*)d_in[13];
    float* out = (float*)d_out;

    float *Q, *Kb, *V, *CTX, *T1, *X1, *H, *T2;
    cudaGetSymbolAddress((void**)&Q,   g_Q);
    cudaGetSymbolAddress((void**)&Kb,  g_Kb);
    cudaGetSymbolAddress((void**)&V,   g_V);
    cudaGetSymbolAddress((void**)&CTX, g_ctx);
    cudaGetSymbolAddress((void**)&T1,  g_t1);
    cudaGetSymbolAddress((void**)&X1,  g_x1);
    cudaGetSymbolAddress((void**)&H,   g_h);
    cudaGetSymbolAddress((void**)&T2,  g_t2);

    cudaFuncSetAttribute(fa_k, cudaFuncAttributeMaxDynamicSharedMemorySize, FA_SMEM);

    const dim3 blk(256);
    auto grd = [](int N, int M) {
        return dim3((unsigned)((N + 127) / 128), (unsigned)((M + 127) / 128), 1);
    };

    // 1-3: Q/K/V projections  [4096,1024] = x @ w
    tgemm_k<0,0><<<grd(D_MODEL, NTOK), blk>>>(x, w_q, Q,  NTOK, D_MODEL, D_MODEL,
        D_MODEL, D_MODEL, D_MODEL, 1.f, nullptr, nullptr);
    tgemm_k<0,0><<<grd(D_MODEL, NTOK), blk>>>(x, w_k, Kb, NTOK, D_MODEL, D_MODEL,
        D_MODEL, D_MODEL, D_MODEL, 1.f, nullptr, nullptr);
    tgemm_k<0,0><<<grd(D_MODEL, NTOK), blk>>>(x, w_v, V,  NTOK, D_MODEL, D_MODEL,
        D_MODEL, D_MODEL, D_MODEL, 1.f, nullptr, nullptr);

    // 4: fused attention (QK^T/8 -> mask -> softmax -> @V), writes ctx
    fa_k<<<dim3(SS / 128, BB * HEADS), blk, FA_SMEM>>>(Q, Kb, V, mask, CTX);

    // 5: t1 = ctx @ w_o + x  (residual)
    tgemm_k<0,EPI_RESID><<<grd(D_MODEL, NTOK), blk>>>(CTX, w_o, T1, NTOK, D_MODEL, D_MODEL,
        D_MODEL, D_MODEL, D_MODEL, 1.f, nullptr, x);

    // 6: x1 = LN1(t1)
    ln_k<<<NTOK, blk>>>(T1, X1, al1, be1);

    // 7: h = relu(x1 @ W1 + b1)
    tgemm_k<0,EPI_BIAS|EPI_RELU><<<grd(D_FF, NTOK), blk>>>(X1, W1, H, NTOK, D_FF, D_MODEL,
        D_MODEL, D_FF, D_FF, 1.f, b1, nullptr);

    // 8: t2 = h @ W2 + b2 + x1 (residual)
    tgemm_k<0,EPI_BIAS|EPI_RESID><<<grd(D_MODEL, NTOK), blk>>>(H, W2, T2, NTOK, D_MODEL, D_FF,
        D_FF, D_MODEL, D_MODEL, 1.f, b2, X1);

    // 9: out = LN2(t2)
    ln_k<<<NTOK, blk>>>(T2, out, al2, be2);
}